// round 13
// baseline (speedup 1.0000x reference)
#include <cuda_runtime.h>
#include <cuda_fp16.h>
#include <math.h>

#define N_NODES 50000
#define N_EDGES 800000
#define IN_CH   64
#define HID     128

// ---------------- scratch (static device globals; no allocation) ----------------
__device__ int   g_cnt[N_NODES];
__device__ int   g_deg[N_NODES];                        // node in-degree (snapshot of counts)
__device__ int   g_off[N_NODES];
__device__ int   g_cur[N_NODES];
__device__ int   g_csr[N_EDGES];                        // src node id per CSR slot (keyed by dst)
__device__ __align__(16) float  g_h[N_NODES * HID];     // hidden activations (fp32, self term)
__device__ __align__(16) __half g_hh[N_NODES * HID];    // hidden activations (fp16, gather copy)
__device__ __align__(16) __half g_xh[N_NODES * IN_CH];  // x in fp16 (gather copy)
__device__ __align__(16) float  g_mean[N_NODES * HID];  // mean-aggregated neighbor features
__device__ __align__(16) float  g_W0[(2 * IN_CH) * HID];// [K][128] k-major: Wl^T rows then Wr^T rows
__device__ __align__(16) float  g_W1[(2 * HID) * HID];
__device__ __align__(16) float  g_W2[(2 * HID) * HID];

// ---------------- packed f32x2 helpers ----------------
__device__ __forceinline__ unsigned long long pack2(float w) {
    unsigned long long r;
    unsigned u = __float_as_uint(w);
    asm("mov.b64 %0, {%1, %1};" : "=l"(r) : "r"(u));
    return r;
}
__device__ __forceinline__ void ffma2(unsigned long long& acc,
                                      unsigned long long a, unsigned long long b) {
    asm("fma.rn.f32x2 %0, %1, %2, %0;" : "+l"(acc) : "l"(a), "l"(b));
}

// ---------------- CSR build (stateless every call) ----------------
__global__ void k_zero_cnt() {
    int i = blockIdx.x * blockDim.x + threadIdx.x;
    if (i < N_NODES) g_cnt[i] = 0;
}

// edge_index is int32 on the wire (JAX x64 disabled downgrades int64 -> int32).
__global__ void k_count(const int* __restrict__ ei) {
    int e = blockIdx.x * blockDim.x + threadIdx.x;
    if (e < N_EDGES) {
        int dst = ei[N_EDGES + e];
        if ((unsigned)dst < (unsigned)N_NODES)
            atomicAdd(&g_cnt[dst], 1);
    }
}

// Single-block exclusive scan of g_cnt -> g_off/g_cur; snapshot degree to g_deg.
__global__ void k_scan_all() {
    __shared__ int s[1024];
    const int t  = threadIdx.x;
    const int CH = (N_NODES + 1023) / 1024;     // 49
    int base = t * CH;
    int end  = base + CH; if (end > N_NODES) end = N_NODES;
    int sum = 0;
    for (int i = base; i < end; i++) sum += g_cnt[i];
    s[t] = sum;
    __syncthreads();
    for (int off = 1; off < 1024; off <<= 1) {
        int v = (t >= off) ? s[t - off] : 0;
        __syncthreads();
        s[t] += v;
        __syncthreads();
    }
    int run = s[t] - sum;                        // exclusive prefix for this chunk
    for (int i = base; i < end; i++) {
        int c = g_cnt[i];
        g_deg[i] = c;
        g_off[i] = run;
        g_cur[i] = run;
        run += c;
    }
}

__global__ void k_fill(const int* __restrict__ ei) {
    int e = blockIdx.x * blockDim.x + threadIdx.x;
    if (e < N_EDGES) {
        int src = ei[e];
        int dst = ei[N_EDGES + e];
        if ((unsigned)dst < (unsigned)N_NODES && (unsigned)src < (unsigned)N_NODES) {
            int pos = atomicAdd(&g_cur[dst], 1);
            if ((unsigned)pos < (unsigned)N_EDGES) g_csr[pos] = src;
        }
    }
}

// ---------------- prep: weight transpose+concat (3 layers) + x fp16 copy ----------------
#define W0_ELEMS  (2 * IN_CH * HID)              // 16384
#define W12_ELEMS (2 * HID * HID)                // 32768
#define X2H_ELEMS (N_NODES * IN_CH / 2)          // half2 count
__global__ void k_prep(const float* __restrict__ x,
                       const float* __restrict__ Wl0, const float* __restrict__ Wr0,
                       const float* __restrict__ Wl1, const float* __restrict__ Wr1,
                       const float* __restrict__ Wl2, const float* __restrict__ Wr2) {
    int i = blockIdx.x * blockDim.x + threadIdx.x;
    if (i < X2H_ELEMS) {
        float2 v = ((const float2*)x)[i];
        ((half2*)g_xh)[i] = __floats2half2_rn(v.x, v.y);
    }
    if (i < W0_ELEMS) {
        int k = i >> 7, f = i & 127;
        g_W0[i] = (k < IN_CH) ? Wl0[f * IN_CH + k] : Wr0[f * IN_CH + (k - IN_CH)];
    }
    if (i < 2 * W12_ELEMS) {
        if (i < W12_ELEMS) {
            int k = i >> 7, f = i & 127;
            g_W1[i] = (k < HID) ? Wl1[f * HID + k] : Wr1[f * HID + (k - HID)];
        } else {
            int j = i - W12_ELEMS;
            int k2 = j >> 7, f2 = j & 127;
            g_W2[j] = (k2 < HID) ? Wl2[f2 * HID + k2] : Wr2[f2 * HID + (k2 - HID)];
        }
    }
}

// ---------------- aggregation d=64 (fp16 src): two nodes per warp ----------------
__global__ void k_agg64h() {
    int w    = (blockIdx.x * blockDim.x + threadIdx.x) >> 5;
    int lane = threadIdx.x & 31;
    int node = w * 2 + (lane >> 4);
    int il   = lane & 15;
    if (node >= N_NODES) return;
    int start = g_off[node];
    int cnt   = g_deg[node];
    const uint2* __restrict__ x2 = (const uint2*)g_xh;   // 16 uint2 per row
    float ax = 0.f, ay = 0.f, az = 0.f, aw = 0.f;
    for (int e = 0; e < cnt; e++) {
        int s = g_csr[start + e];
        uint2 v = x2[(size_t)s * 16 + il];
        float2 lo = __half22float2(*(const half2*)&v.x);
        float2 hi = __half22float2(*(const half2*)&v.y);
        ax += lo.x; ay += lo.y; az += hi.x; aw += hi.y;
    }
    float inv = 1.f / fmaxf((float)cnt, 1.f);
    ((float4*)g_mean)[(size_t)node * 16 + il] =
        make_float4(ax * inv, ay * inv, az * inv, aw * inv);
}

// ---------------- aggregation d=128 (fp16 src): warp per node ----------------
__global__ void k_agg128h() {
    int gw   = (blockIdx.x * blockDim.x + threadIdx.x) >> 5;
    int lane = threadIdx.x & 31;
    if (gw >= N_NODES) return;
    int start = g_off[gw];
    int cnt   = g_deg[gw];
    const uint2* __restrict__ h2 = (const uint2*)g_hh;   // 32 uint2 per row
    float ax = 0.f, ay = 0.f, az = 0.f, aw = 0.f;
    for (int e = 0; e < cnt; e++) {
        int s = g_csr[start + e];
        uint2 v = h2[(size_t)s * 32 + lane];
        float2 lo = __half22float2(*(const half2*)&v.x);
        float2 hi = __half22float2(*(const half2*)&v.y);
        ax += lo.x; ay += lo.y; az += hi.x; aw += hi.y;
    }
    float inv = 1.f / fmaxf((float)cnt, 1.f);
    ((float4*)g_mean)[(size_t)gw * 32 + lane] =
        make_float4(ax * inv, ay * inv, az * inv, aw * inv);
}

// ---------------- fused transform + L2-normalize (+relu) — R8-proven body ----------------
// out = normalize(mean@Wl^T + bias + x@Wr^T), K = 2*DIN virtual reduction.
// Block: 256 threads, tile 128 nodes x 128 f. Thread: 8 nodes x 8 cols,
// node-pair-packed f32x2 accumulators (bias folded into init).
// When writing g_h, also writes fp16 copy g_hh for the next gather.
#define AS_STRIDE 130
__global__ __launch_bounds__(256) void k_transform(
    const float* __restrict__ xin, int use_h, int layer,
    const float* __restrict__ bias, int DIN, int relu, int to_out,
    float* __restrict__ dout)
{
    const float* __restrict__ A1 = g_mean;
    const float* __restrict__ A2 = use_h ? g_h : xin;
    const float* __restrict__ W  = (layer == 0) ? g_W0 : (layer == 1) ? g_W1 : g_W2;

    __shared__ __align__(16) float As[32 * AS_STRIDE];  // [kk][node]
    __shared__ __align__(16) float Ws[32 * 128];        // [kk][f]

    const int tid   = threadIdx.x;
    const int tx    = tid & 15;          // f group
    const int ty    = tid >> 4;          // node group
    const int f0    = tx * 8;
    const int nl0   = ty * 8;
    const int node0 = blockIdx.x * 128;

    float bs[8];
#pragma unroll
    for (int j = 0; j < 8; j++) bs[j] = bias[f0 + j];

    unsigned long long acc[4][8];        // [node pair][col], bias preloaded
#pragma unroll
    for (int p = 0; p < 4; p++)
#pragma unroll
        for (int j = 0; j < 8; j++) acc[p][j] = pack2(bs[j]);

    const int K   = 2 * DIN;
    const int lkk = tid & 31;            // A loader: k within chunk
    const int lng = tid >> 5;            // A loader: node group (16 nodes)
    const int lf  = tid & 127;           // W loader: f
    const int lkg = tid >> 7;            // W loader: k group (16 kk)

    for (int c0 = 0; c0 < K; c0 += 32) {
        const float* Asrc = (c0 < DIN) ? A1 : A2;
        const int cb = (c0 < DIN) ? c0 : (c0 - DIN);
#pragma unroll
        for (int r = 0; r < 16; r++) {
            int n = lng * 16 + r;
            int node = node0 + n;
            float v = (node < N_NODES) ? Asrc[(size_t)node * DIN + cb + lkk] : 0.f;
            As[lkk * AS_STRIDE + n] = v;
        }
#pragma unroll
        for (int r = 0; r < 16; r++) {
            int kk = lkg * 16 + r;
            Ws[kk * 128 + lf] = W[(size_t)(c0 + kk) * 128 + lf];
        }
        __syncthreads();

#pragma unroll
        for (int kk = 0; kk < 32; kk++) {
            const unsigned long long* ap =
                (const unsigned long long*)&As[kk * AS_STRIDE + nl0];
            unsigned long long a0 = ap[0], a1 = ap[1], a2 = ap[2], a3 = ap[3];
            float4 w0 = *(const float4*)&Ws[kk * 128 + f0];
            float4 w1 = *(const float4*)&Ws[kk * 128 + f0 + 4];
            unsigned long long wd[8] = {
                pack2(w0.x), pack2(w0.y), pack2(w0.z), pack2(w0.w),
                pack2(w1.x), pack2(w1.y), pack2(w1.z), pack2(w1.w)};
#pragma unroll
            for (int j = 0; j < 8; j++) {
                ffma2(acc[0][j], a0, wd[j]);
                ffma2(acc[1][j], a1, wd[j]);
                ffma2(acc[2][j], a2, wd[j]);
                ffma2(acc[3][j], a3, wd[j]);
            }
        }
        __syncthreads();
    }

    // ---- epilogue: L2 norm over 16 tx lanes, relu, store (fp32 + fp16 copy) ----
    float vals[8][8];                    // [node 0..7][col]
#pragma unroll
    for (int p = 0; p < 4; p++)
#pragma unroll
        for (int j = 0; j < 8; j++) {
            unsigned long long v = acc[p][j];
            vals[2 * p    ][j] = __uint_as_float((unsigned)(v & 0xffffffffull));
            vals[2 * p + 1][j] = __uint_as_float((unsigned)(v >> 32));
        }

    float ss[8];
#pragma unroll
    for (int i = 0; i < 8; i++) {
        float s = 0.f;
#pragma unroll
        for (int j = 0; j < 8; j++) s += vals[i][j] * vals[i][j];
        ss[i] = s;
    }
#pragma unroll
    for (int m = 1; m < 16; m <<= 1)
#pragma unroll
        for (int i = 0; i < 8; i++)
            ss[i] += __shfl_xor_sync(0xffffffffu, ss[i], m);

    float* __restrict__ dest = to_out ? dout : g_h;
#pragma unroll
    for (int i = 0; i < 8; i++) {
        int node = node0 + nl0 + i;
        if (node < N_NODES) {
            float scale = 1.f / fmaxf(sqrtf(ss[i]), 1e-12f);
            float o[8];
#pragma unroll
            for (int j = 0; j < 8; j++) {
                float v = vals[i][j] * scale;
                o[j] = relu ? fmaxf(v, 0.f) : v;
            }
            *(float4*)&dest[(size_t)node * 128 + f0] =
                make_float4(o[0], o[1], o[2], o[3]);
            *(float4*)&dest[(size_t)node * 128 + f0 + 4] =
                make_float4(o[4], o[5], o[6], o[7]);
            if (!to_out) {
                half2 hh[4];
                hh[0] = __floats2half2_rn(o[0], o[1]);
                hh[1] = __floats2half2_rn(o[2], o[3]);
                hh[2] = __floats2half2_rn(o[4], o[5]);
                hh[3] = __floats2half2_rn(o[6], o[7]);
                *(uint4*)&g_hh[(size_t)node * 128 + f0] = *(const uint4*)hh;
            }
        }
    }
}

// ---------------- launch (11 kernels, fully stateless) ----------------
extern "C" void kernel_launch(void* const* d_in, const int* in_sizes, int n_in,
                              void* d_out, int out_size) {
    const float* x   = (const float*)d_in[0];
    const int*   ei  = (const int*)d_in[1];     // int32 (JAX x64-disabled)
    const float* Wl0 = (const float*)d_in[2];
    const float* bl0 = (const float*)d_in[3];
    const float* Wr0 = (const float*)d_in[4];
    const float* Wl1 = (const float*)d_in[5];
    const float* bl1 = (const float*)d_in[6];
    const float* Wr1 = (const float*)d_in[7];
    const float* Wl2 = (const float*)d_in[8];
    const float* bl2 = (const float*)d_in[9];
    const float* Wr2 = (const float*)d_in[10];
    float* out = (float*)d_out;

    const int NB_NODE   = (N_NODES + 255) / 256;
    const int NB_EDGE   = (N_EDGES + 255) / 256;
    const int NB_AGG128 = (N_NODES + 7) / 8;
    const int NB_AGG64  = (N_NODES / 2 + 7) / 8;
    const int NB_TRANS  = (N_NODES + 127) / 128;
    const int NB_PREP   = (X2H_ELEMS + 255) / 256;   // covers all prep jobs

    // prep (weights + fp16 x) — independent of CSR
    k_prep<<<NB_PREP, 256>>>(x, Wl0, Wr0, Wl1, Wr1, Wl2, Wr2);

    // CSR build
    k_zero_cnt<<<NB_NODE, 256>>>();
    k_count<<<NB_EDGE, 256>>>(ei);
    k_scan_all<<<1, 1024>>>();
    k_fill<<<NB_EDGE, 256>>>(ei);

    // layer 0: x (d=64) -> g_h/g_hh (relu)
    k_agg64h<<<NB_AGG64, 256>>>();
    k_transform<<<NB_TRANS, 256>>>(x, 0, 0, bl0, IN_CH, 1, 0, out);

    // layer 1: g_hh (d=128) -> g_h/g_hh (relu)
    k_agg128h<<<NB_AGG128, 256>>>();
    k_transform<<<NB_TRANS, 256>>>(x, 1, 1, bl1, HID, 1, 0, out);

    // layer 2: g_hh (d=128) -> out (no relu)
    k_agg128h<<<NB_AGG128, 256>>>();
    k_transform<<<NB_TRANS, 256>>>(x, 1, 2, bl2, HID, 0, 1, out);
}

// round 14
// speedup vs baseline: 1.0003x; 1.0003x over previous
#include <cuda_runtime.h>
#include <cuda_fp16.h>
#include <math.h>

#define N_NODES 50000
#define N_EDGES 800000
#define IN_CH   64
#define HID     128

// ---------------- scratch (static device globals; no allocation) ----------------
__device__ int   g_cnt[N_NODES];
__device__ int   g_deg[N_NODES];                        // node in-degree (snapshot of counts)
__device__ int   g_off[N_NODES];
__device__ int   g_cur[N_NODES];
__device__ int   g_csr[N_EDGES];                        // src node id per CSR slot (keyed by dst)
__device__ __align__(16) float  g_h[N_NODES * HID];     // hidden activations (fp32, self term)
__device__ __align__(16) __half g_hh[N_NODES * HID];    // hidden activations (fp16, gather copy)
__device__ __align__(16) __half g_xh[N_NODES * IN_CH];  // x in fp16 (gather copy)
__device__ __align__(16) float  g_mean[N_NODES * HID];  // mean-aggregated neighbor features
__device__ __align__(16) float  g_W0[(2 * IN_CH) * HID];// [K][128] k-major: Wl^T rows then Wr^T rows
__device__ __align__(16) float  g_W1[(2 * HID) * HID];
__device__ __align__(16) float  g_W2[(2 * HID) * HID];

// ---------------- packed f32x2 helpers ----------------
__device__ __forceinline__ unsigned long long pack2(float w) {
    unsigned long long r;
    unsigned u = __float_as_uint(w);
    asm("mov.b64 %0, {%1, %1};" : "=l"(r) : "r"(u));
    return r;
}
__device__ __forceinline__ void ffma2(unsigned long long& acc,
                                      unsigned long long a, unsigned long long b) {
    asm("fma.rn.f32x2 %0, %1, %2, %0;" : "+l"(acc) : "l"(a), "l"(b));
}

// ---------------- CSR build (stateless every call) ----------------
__global__ void k_zero_cnt() {
    int i = blockIdx.x * blockDim.x + threadIdx.x;
    if (i < N_NODES) g_cnt[i] = 0;
}

// edge_index is int32 on the wire (JAX x64 disabled downgrades int64 -> int32).
__global__ void k_count(const int* __restrict__ ei) {
    int e = blockIdx.x * blockDim.x + threadIdx.x;
    if (e < N_EDGES) {
        int dst = ei[N_EDGES + e];
        if ((unsigned)dst < (unsigned)N_NODES)
            atomicAdd(&g_cnt[dst], 1);
    }
}

// Single-block exclusive scan of g_cnt -> g_off/g_cur; snapshot degree to g_deg.
__global__ void k_scan_all() {
    __shared__ int s[1024];
    const int t  = threadIdx.x;
    const int CH = (N_NODES + 1023) / 1024;     // 49
    int base = t * CH;
    int end  = base + CH; if (end > N_NODES) end = N_NODES;
    int sum = 0;
    for (int i = base; i < end; i++) sum += g_cnt[i];
    s[t] = sum;
    __syncthreads();
    for (int off = 1; off < 1024; off <<= 1) {
        int v = (t >= off) ? s[t - off] : 0;
        __syncthreads();
        s[t] += v;
        __syncthreads();
    }
    int run = s[t] - sum;                        // exclusive prefix for this chunk
    for (int i = base; i < end; i++) {
        int c = g_cnt[i];
        g_deg[i] = c;
        g_off[i] = run;
        g_cur[i] = run;
        run += c;
    }
}

__global__ void k_fill(const int* __restrict__ ei) {
    int e = blockIdx.x * blockDim.x + threadIdx.x;
    if (e < N_EDGES) {
        int src = ei[e];
        int dst = ei[N_EDGES + e];
        if ((unsigned)dst < (unsigned)N_NODES && (unsigned)src < (unsigned)N_NODES) {
            int pos = atomicAdd(&g_cur[dst], 1);
            if ((unsigned)pos < (unsigned)N_EDGES) g_csr[pos] = src;
        }
    }
}

// ---------------- prep: weight transpose+concat (3 layers) + x fp16 copy ----------------
#define W0_ELEMS  (2 * IN_CH * HID)              // 16384
#define W12_ELEMS (2 * HID * HID)                // 32768
#define X2H_ELEMS (N_NODES * IN_CH / 2)          // half2 count
__global__ void k_prep(const float* __restrict__ x,
                       const float* __restrict__ Wl0, const float* __restrict__ Wr0,
                       const float* __restrict__ Wl1, const float* __restrict__ Wr1,
                       const float* __restrict__ Wl2, const float* __restrict__ Wr2) {
    int i = blockIdx.x * blockDim.x + threadIdx.x;
    if (i < X2H_ELEMS) {
        float2 v = ((const float2*)x)[i];
        ((half2*)g_xh)[i] = __floats2half2_rn(v.x, v.y);
    }
    if (i < W0_ELEMS) {
        int k = i >> 7, f = i & 127;
        g_W0[i] = (k < IN_CH) ? Wl0[f * IN_CH + k] : Wr0[f * IN_CH + (k - IN_CH)];
    }
    if (i < 2 * W12_ELEMS) {
        if (i < W12_ELEMS) {
            int k = i >> 7, f = i & 127;
            g_W1[i] = (k < HID) ? Wl1[f * HID + k] : Wr1[f * HID + (k - HID)];
        } else {
            int j = i - W12_ELEMS;
            int k2 = j >> 7, f2 = j & 127;
            g_W2[j] = (k2 < HID) ? Wl2[f2 * HID + k2] : Wr2[f2 * HID + (k2 - HID)];
        }
    }
}

// ---------------- aggregation d=64 (fp16 src): two nodes per warp ----------------
__global__ void k_agg64h() {
    int w    = (blockIdx.x * blockDim.x + threadIdx.x) >> 5;
    int lane = threadIdx.x & 31;
    int node = w * 2 + (lane >> 4);
    int il   = lane & 15;
    if (node >= N_NODES) return;
    int start = g_off[node];
    int cnt   = g_deg[node];
    const uint2* __restrict__ x2 = (const uint2*)g_xh;   // 16 uint2 per row
    float ax = 0.f, ay = 0.f, az = 0.f, aw = 0.f;
    for (int e = 0; e < cnt; e++) {
        int s = g_csr[start + e];
        uint2 v = x2[(size_t)s * 16 + il];
        float2 lo = __half22float2(*(const half2*)&v.x);
        float2 hi = __half22float2(*(const half2*)&v.y);
        ax += lo.x; ay += lo.y; az += hi.x; aw += hi.y;
    }
    float inv = 1.f / fmaxf((float)cnt, 1.f);
    ((float4*)g_mean)[(size_t)node * 16 + il] =
        make_float4(ax * inv, ay * inv, az * inv, aw * inv);
}

// ---------------- aggregation d=128 (fp16 src): warp per node ----------------
__global__ void k_agg128h() {
    int gw   = (blockIdx.x * blockDim.x + threadIdx.x) >> 5;
    int lane = threadIdx.x & 31;
    if (gw >= N_NODES) return;
    int start = g_off[gw];
    int cnt   = g_deg[gw];
    const uint2* __restrict__ h2 = (const uint2*)g_hh;   // 32 uint2 per row
    float ax = 0.f, ay = 0.f, az = 0.f, aw = 0.f;
    for (int e = 0; e < cnt; e++) {
        int s = g_csr[start + e];
        uint2 v = h2[(size_t)s * 32 + lane];
        float2 lo = __half22float2(*(const half2*)&v.x);
        float2 hi = __half22float2(*(const half2*)&v.y);
        ax += lo.x; ay += lo.y; az += hi.x; aw += hi.y;
    }
    float inv = 1.f / fmaxf((float)cnt, 1.f);
    ((float4*)g_mean)[(size_t)gw * 32 + lane] =
        make_float4(ax * inv, ay * inv, az * inv, aw * inv);
}

// ---------------- fused transform + L2-normalize (+relu) — R8-proven body ----------------
// out = normalize(mean@Wl^T + bias + x@Wr^T), K = 2*DIN virtual reduction.
// Block: 256 threads, tile 128 nodes x 128 f. Thread: 8 nodes x 8 cols,
// node-pair-packed f32x2 accumulators (bias folded into init).
// When writing g_h, also writes fp16 copy g_hh for the next gather.
#define AS_STRIDE 130
__global__ __launch_bounds__(256) void k_transform(
    const float* __restrict__ xin, int use_h, int layer,
    const float* __restrict__ bias, int DIN, int relu, int to_out,
    float* __restrict__ dout)
{
    const float* __restrict__ A1 = g_mean;
    const float* __restrict__ A2 = use_h ? g_h : xin;
    const float* __restrict__ W  = (layer == 0) ? g_W0 : (layer == 1) ? g_W1 : g_W2;

    __shared__ __align__(16) float As[32 * AS_STRIDE];  // [kk][node]
    __shared__ __align__(16) float Ws[32 * 128];        // [kk][f]

    const int tid   = threadIdx.x;
    const int tx    = tid & 15;          // f group
    const int ty    = tid >> 4;          // node group
    const int f0    = tx * 8;
    const int nl0   = ty * 8;
    const int node0 = blockIdx.x * 128;

    float bs[8];
#pragma unroll
    for (int j = 0; j < 8; j++) bs[j] = bias[f0 + j];

    unsigned long long acc[4][8];        // [node pair][col], bias preloaded
#pragma unroll
    for (int p = 0; p < 4; p++)
#pragma unroll
        for (int j = 0; j < 8; j++) acc[p][j] = pack2(bs[j]);

    const int K   = 2 * DIN;
    const int lkk = tid & 31;            // A loader: k within chunk
    const int lng = tid >> 5;            // A loader: node group (16 nodes)
    const int lf  = tid & 127;           // W loader: f
    const int lkg = tid >> 7;            // W loader: k group (16 kk)

    for (int c0 = 0; c0 < K; c0 += 32) {
        const float* Asrc = (c0 < DIN) ? A1 : A2;
        const int cb = (c0 < DIN) ? c0 : (c0 - DIN);
#pragma unroll
        for (int r = 0; r < 16; r++) {
            int n = lng * 16 + r;
            int node = node0 + n;
            float v = (node < N_NODES) ? Asrc[(size_t)node * DIN + cb + lkk] : 0.f;
            As[lkk * AS_STRIDE + n] = v;
        }
#pragma unroll
        for (int r = 0; r < 16; r++) {
            int kk = lkg * 16 + r;
            Ws[kk * 128 + lf] = W[(size_t)(c0 + kk) * 128 + lf];
        }
        __syncthreads();

#pragma unroll
        for (int kk = 0; kk < 32; kk++) {
            const unsigned long long* ap =
                (const unsigned long long*)&As[kk * AS_STRIDE + nl0];
            unsigned long long a0 = ap[0], a1 = ap[1], a2 = ap[2], a3 = ap[3];
            float4 w0 = *(const float4*)&Ws[kk * 128 + f0];
            float4 w1 = *(const float4*)&Ws[kk * 128 + f0 + 4];
            unsigned long long wd[8] = {
                pack2(w0.x), pack2(w0.y), pack2(w0.z), pack2(w0.w),
                pack2(w1.x), pack2(w1.y), pack2(w1.z), pack2(w1.w)};
#pragma unroll
            for (int j = 0; j < 8; j++) {
                ffma2(acc[0][j], a0, wd[j]);
                ffma2(acc[1][j], a1, wd[j]);
                ffma2(acc[2][j], a2, wd[j]);
                ffma2(acc[3][j], a3, wd[j]);
            }
        }
        __syncthreads();
    }

    // ---- epilogue: L2 norm over 16 tx lanes, relu, store (fp32 + fp16 copy) ----
    float vals[8][8];                    // [node 0..7][col]
#pragma unroll
    for (int p = 0; p < 4; p++)
#pragma unroll
        for (int j = 0; j < 8; j++) {
            unsigned long long v = acc[p][j];
            vals[2 * p    ][j] = __uint_as_float((unsigned)(v & 0xffffffffull));
            vals[2 * p + 1][j] = __uint_as_float((unsigned)(v >> 32));
        }

    float ss[8];
#pragma unroll
    for (int i = 0; i < 8; i++) {
        float s = 0.f;
#pragma unroll
        for (int j = 0; j < 8; j++) s += vals[i][j] * vals[i][j];
        ss[i] = s;
    }
#pragma unroll
    for (int m = 1; m < 16; m <<= 1)
#pragma unroll
        for (int i = 0; i < 8; i++)
            ss[i] += __shfl_xor_sync(0xffffffffu, ss[i], m);

    float* __restrict__ dest = to_out ? dout : g_h;
#pragma unroll
    for (int i = 0; i < 8; i++) {
        int node = node0 + nl0 + i;
        if (node < N_NODES) {
            float scale = 1.f / fmaxf(sqrtf(ss[i]), 1e-12f);
            float o[8];
#pragma unroll
            for (int j = 0; j < 8; j++) {
                float v = vals[i][j] * scale;
                o[j] = relu ? fmaxf(v, 0.f) : v;
            }
            *(float4*)&dest[(size_t)node * 128 + f0] =
                make_float4(o[0], o[1], o[2], o[3]);
            *(float4*)&dest[(size_t)node * 128 + f0 + 4] =
                make_float4(o[4], o[5], o[6], o[7]);
            if (!to_out) {
                half2 hh[4];
                hh[0] = __floats2half2_rn(o[0], o[1]);
                hh[1] = __floats2half2_rn(o[2], o[3]);
                hh[2] = __floats2half2_rn(o[4], o[5]);
                hh[3] = __floats2half2_rn(o[6], o[7]);
                *(uint4*)&g_hh[(size_t)node * 128 + f0] = *(const uint4*)hh;
            }
        }
    }
}

// ---------------- launch (11 kernels, fully stateless) ----------------
extern "C" void kernel_launch(void* const* d_in, const int* in_sizes, int n_in,
                              void* d_out, int out_size) {
    const float* x   = (const float*)d_in[0];
    const int*   ei  = (const int*)d_in[1];     // int32 (JAX x64-disabled)
    const float* Wl0 = (const float*)d_in[2];
    const float* bl0 = (const float*)d_in[3];
    const float* Wr0 = (const float*)d_in[4];
    const float* Wl1 = (const float*)d_in[5];
    const float* bl1 = (const float*)d_in[6];
    const float* Wr1 = (const float*)d_in[7];
    const float* Wl2 = (const float*)d_in[8];
    const float* bl2 = (const float*)d_in[9];
    const float* Wr2 = (const float*)d_in[10];
    float* out = (float*)d_out;

    const int NB_NODE   = (N_NODES + 255) / 256;
    const int NB_EDGE   = (N_EDGES + 255) / 256;
    const int NB_AGG128 = (N_NODES + 7) / 8;
    const int NB_AGG64  = (N_NODES / 2 + 7) / 8;
    const int NB_TRANS  = (N_NODES + 127) / 128;
    const int NB_PREP   = (X2H_ELEMS + 255) / 256;   // covers all prep jobs

    // prep (weights + fp16 x) — independent of CSR
    k_prep<<<NB_PREP, 256>>>(x, Wl0, Wr0, Wl1, Wr1, Wl2, Wr2);

    // CSR build
    k_zero_cnt<<<NB_NODE, 256>>>();
    k_count<<<NB_EDGE, 256>>>(ei);
    k_scan_all<<<1, 1024>>>();
    k_fill<<<NB_EDGE, 256>>>(ei);

    // layer 0: x (d=64) -> g_h/g_hh (relu)
    k_agg64h<<<NB_AGG64, 256>>>();
    k_transform<<<NB_TRANS, 256>>>(x, 0, 0, bl0, IN_CH, 1, 0, out);

    // layer 1: g_hh (d=128) -> g_h/g_hh (relu)
    k_agg128h<<<NB_AGG128, 256>>>();
    k_transform<<<NB_TRANS, 256>>>(x, 1, 1, bl1, HID, 1, 0, out);

    // layer 2: g_hh (d=128) -> out (no relu)
    k_agg128h<<<NB_AGG128, 256>>>();
    k_transform<<<NB_TRANS, 256>>>(x, 1, 2, bl2, HID, 0, 1, out);
}

// round 16
// speedup vs baseline: 1.2752x; 1.2748x over previous
#include <cuda_runtime.h>
#include <cuda_fp16.h>
#include <math.h>

#define N_NODES 50000
#define N_EDGES 800000
#define IN_CH   64
#define HID     128

// ---------------- scratch (static device globals; no allocation) ----------------
__device__ int   g_cnt[N_NODES];
__device__ int   g_deg[N_NODES];                        // node in-degree (snapshot)
__device__ int   g_off[N_NODES];
__device__ int   g_cur[N_NODES];
__device__ int   g_bsum[256];
__device__ int   g_csr[N_EDGES];                        // src node id per CSR slot (keyed by dst)
__device__ __align__(16) float  g_h[N_NODES * HID];     // hidden activations (fp32, self term)
__device__ __align__(16) __half g_hh[N_NODES * HID];    // hidden activations (fp16, gather copy)
__device__ __align__(16) __half g_xh[N_NODES * IN_CH];  // x in fp16 (gather copy)
__device__ __align__(16) float  g_mean[N_NODES * HID];  // mean-aggregated neighbor features
__device__ __align__(16) float  g_W0[(2 * IN_CH) * HID];// [K][128] k-major: Wl^T rows then Wr^T rows
__device__ __align__(16) float  g_W1[(2 * HID) * HID];
__device__ __align__(16) float  g_W2[(2 * HID) * HID];

// ---------------- packed f32x2 helpers ----------------
__device__ __forceinline__ unsigned long long pack2(float w) {
    unsigned long long r;
    unsigned u = __float_as_uint(w);
    asm("mov.b64 %0, {%1, %1};" : "=l"(r) : "r"(u));
    return r;
}
__device__ __forceinline__ void ffma2(unsigned long long& acc,
                                      unsigned long long a, unsigned long long b) {
    asm("fma.rn.f32x2 %0, %1, %2, %0;" : "+l"(acc) : "l"(a), "l"(b));
}

// ---------------- CSR build (multi-block scan, R4-proven shape) ----------------
__global__ void k_zero_cnt() {
    int i = blockIdx.x * blockDim.x + threadIdx.x;
    if (i < N_NODES) g_cnt[i] = 0;
}

// edge_index is int32 on the wire (JAX x64 disabled downgrades int64 -> int32).
__global__ void k_count(const int* __restrict__ ei) {
    int e = blockIdx.x * blockDim.x + threadIdx.x;
    if (e < N_EDGES) {
        int dst = ei[N_EDGES + e];
        if ((unsigned)dst < (unsigned)N_NODES)
            atomicAdd(&g_cnt[dst], 1);
    }
}

__global__ void k_scan1() {
    __shared__ int s[256];
    int i = blockIdx.x * 256 + threadIdx.x;
    int v = (i < N_NODES) ? g_cnt[i] : 0;
    s[threadIdx.x] = v;
    __syncthreads();
    for (int off = 1; off < 256; off <<= 1) {
        int t = (threadIdx.x >= off) ? s[threadIdx.x - off] : 0;
        __syncthreads();
        s[threadIdx.x] += t;
        __syncthreads();
    }
    if (i < N_NODES) g_off[i] = s[threadIdx.x] - v;   // exclusive within block
    if (threadIdx.x == 255) g_bsum[blockIdx.x] = s[255];
}

__global__ void k_scan2(int nb) {
    __shared__ int s[256];
    int v = (threadIdx.x < nb) ? g_bsum[threadIdx.x] : 0;
    s[threadIdx.x] = v;
    __syncthreads();
    for (int off = 1; off < 256; off <<= 1) {
        int t = (threadIdx.x >= off) ? s[threadIdx.x - off] : 0;
        __syncthreads();
        s[threadIdx.x] += t;
        __syncthreads();
    }
    g_bsum[threadIdx.x] = s[threadIdx.x] - v;         // exclusive block offsets
}

__global__ void k_scan3() {
    int i = blockIdx.x * blockDim.x + threadIdx.x;
    if (i < N_NODES) {
        int o = g_off[i] + g_bsum[i >> 8];
        g_off[i] = o;
        g_cur[i] = o;
        g_deg[i] = g_cnt[i];
    }
}

__global__ void k_fill(const int* __restrict__ ei) {
    int e = blockIdx.x * blockDim.x + threadIdx.x;
    if (e < N_EDGES) {
        int src = ei[e];
        int dst = ei[N_EDGES + e];
        if ((unsigned)dst < (unsigned)N_NODES && (unsigned)src < (unsigned)N_NODES) {
            int pos = atomicAdd(&g_cur[dst], 1);
            if ((unsigned)pos < (unsigned)N_EDGES) g_csr[pos] = src;
        }
    }
}

// ---------------- prep: weight transpose+concat (3 layers) + x fp16 copy ----------------
#define W0_ELEMS  (2 * IN_CH * HID)              // 16384
#define W12_ELEMS (2 * HID * HID)                // 32768
#define X2H_ELEMS (N_NODES * IN_CH / 2)          // half2 count
__global__ void k_prep(const float* __restrict__ x,
                       const float* __restrict__ Wl0, const float* __restrict__ Wr0,
                       const float* __restrict__ Wl1, const float* __restrict__ Wr1,
                       const float* __restrict__ Wl2, const float* __restrict__ Wr2) {
    int i = blockIdx.x * blockDim.x + threadIdx.x;
    if (i < X2H_ELEMS) {
        float2 v = ((const float2*)x)[i];
        ((half2*)g_xh)[i] = __floats2half2_rn(v.x, v.y);
    }
    if (i < W0_ELEMS) {
        int k = i >> 7, f = i & 127;
        g_W0[i] = (k < IN_CH) ? Wl0[f * IN_CH + k] : Wr0[f * IN_CH + (k - IN_CH)];
    }
    if (i < 2 * W12_ELEMS) {
        if (i < W12_ELEMS) {
            int k = i >> 7, f = i & 127;
            g_W1[i] = (k < HID) ? Wl1[f * HID + k] : Wr1[f * HID + (k - HID)];
        } else {
            int j = i - W12_ELEMS;
            int k2 = j >> 7, f2 = j & 127;
            g_W2[j] = (k2 < HID) ? Wl2[f2 * HID + k2] : Wr2[f2 * HID + (k2 - HID)];
        }
    }
}

// ---------------- aggregation d=64 (fp16 src): two nodes per warp ----------------
__global__ void k_agg64h() {
    int w    = (blockIdx.x * blockDim.x + threadIdx.x) >> 5;
    int lane = threadIdx.x & 31;
    int node = w * 2 + (lane >> 4);
    int il   = lane & 15;
    if (node >= N_NODES) return;
    int start = g_off[node];
    int cnt   = g_deg[node];
    const uint2* __restrict__ x2 = (const uint2*)g_xh;   // 16 uint2 per row
    float ax = 0.f, ay = 0.f, az = 0.f, aw = 0.f;
    for (int e = 0; e < cnt; e++) {
        int s = g_csr[start + e];
        uint2 v = x2[(size_t)s * 16 + il];
        float2 lo = __half22float2(*(const half2*)&v.x);
        float2 hi = __half22float2(*(const half2*)&v.y);
        ax += lo.x; ay += lo.y; az += hi.x; aw += hi.y;
    }
    float inv = 1.f / fmaxf((float)cnt, 1.f);
    ((float4*)g_mean)[(size_t)node * 16 + il] =
        make_float4(ax * inv, ay * inv, az * inv, aw * inv);
}

// ---------------- aggregation d=128 (fp16 src): warp per node ----------------
__global__ void k_agg128h() {
    int gw   = (blockIdx.x * blockDim.x + threadIdx.x) >> 5;
    int lane = threadIdx.x & 31;
    if (gw >= N_NODES) return;
    int start = g_off[gw];
    int cnt   = g_deg[gw];
    const uint2* __restrict__ h2 = (const uint2*)g_hh;   // 32 uint2 per row
    float ax = 0.f, ay = 0.f, az = 0.f, aw = 0.f;
    for (int e = 0; e < cnt; e++) {
        int s = g_csr[start + e];
        uint2 v = h2[(size_t)s * 32 + lane];
        float2 lo = __half22float2(*(const half2*)&v.x);
        float2 hi = __half22float2(*(const half2*)&v.y);
        ax += lo.x; ay += lo.y; az += hi.x; aw += hi.y;
    }
    float inv = 1.f / fmaxf((float)cnt, 1.f);
    ((float4*)g_mean)[(size_t)gw * 32 + lane] =
        make_float4(ax * inv, ay * inv, az * inv, aw * inv);
}

// ---------------- fused transform + L2-normalize (+relu) — R8-proven body ----------------
// out = normalize(mean@Wl^T + bias + x@Wr^T), K = 2*DIN virtual reduction.
// Block: 256 threads, tile 128 nodes x 128 f. Thread: 8 nodes x 8 cols,
// node-pair-packed f32x2 accumulators (bias folded into init).
// When writing g_h, also writes fp16 copy g_hh for the next gather.
#define AS_STRIDE 130
__global__ __launch_bounds__(256) void k_transform(
    const float* __restrict__ xin, int use_h, int layer,
    const float* __restrict__ bias, int DIN, int relu, int to_out,
    float* __restrict__ dout)
{
    const float* __restrict__ A1 = g_mean;
    const float* __restrict__ A2 = use_h ? g_h : xin;
    const float* __restrict__ W  = (layer == 0) ? g_W0 : (layer == 1) ? g_W1 : g_W2;

    __shared__ __align__(16) float As[32 * AS_STRIDE];  // [kk][node]
    __shared__ __align__(16) float Ws[32 * 128];        // [kk][f]

    const int tid   = threadIdx.x;
    const int tx    = tid & 15;          // f group
    const int ty    = tid >> 4;          // node group
    const int f0    = tx * 8;
    const int nl0   = ty * 8;
    const int node0 = blockIdx.x * 128;

    float bs[8];
#pragma unroll
    for (int j = 0; j < 8; j++) bs[j] = bias[f0 + j];

    unsigned long long acc[4][8];        // [node pair][col], bias preloaded
#pragma unroll
    for (int p = 0; p < 4; p++)
#pragma unroll
        for (int j = 0; j < 8; j++) acc[p][j] = pack2(bs[j]);

    const int K   = 2 * DIN;
    const int lkk = tid & 31;            // A loader: k within chunk
    const int lng = tid >> 5;            // A loader: node group (16 nodes)
    const int lf  = tid & 127;           // W loader: f
    const int lkg = tid >> 7;            // W loader: k group (16 kk)

    for (int c0 = 0; c0 < K; c0 += 32) {
        const float* Asrc = (c0 < DIN) ? A1 : A2;
        const int cb = (c0 < DIN) ? c0 : (c0 - DIN);
#pragma unroll
        for (int r = 0; r < 16; r++) {
            int n = lng * 16 + r;
            int node = node0 + n;
            float v = (node < N_NODES) ? Asrc[(size_t)node * DIN + cb + lkk] : 0.f;
            As[lkk * AS_STRIDE + n] = v;
        }
#pragma unroll
        for (int r = 0; r < 16; r++) {
            int kk = lkg * 16 + r;
            Ws[kk * 128 + lf] = W[(size_t)(c0 + kk) * 128 + lf];
        }
        __syncthreads();

#pragma unroll
        for (int kk = 0; kk < 32; kk++) {
            const unsigned long long* ap =
                (const unsigned long long*)&As[kk * AS_STRIDE + nl0];
            unsigned long long a0 = ap[0], a1 = ap[1], a2 = ap[2], a3 = ap[3];
            float4 w0 = *(const float4*)&Ws[kk * 128 + f0];
            float4 w1 = *(const float4*)&Ws[kk * 128 + f0 + 4];
            unsigned long long wd[8] = {
                pack2(w0.x), pack2(w0.y), pack2(w0.z), pack2(w0.w),
                pack2(w1.x), pack2(w1.y), pack2(w1.z), pack2(w1.w)};
#pragma unroll
            for (int j = 0; j < 8; j++) {
                ffma2(acc[0][j], a0, wd[j]);
                ffma2(acc[1][j], a1, wd[j]);
                ffma2(acc[2][j], a2, wd[j]);
                ffma2(acc[3][j], a3, wd[j]);
            }
        }
        __syncthreads();
    }

    // ---- epilogue: L2 norm over 16 tx lanes, relu, store (fp32 + fp16 copy) ----
    float vals[8][8];                    // [node 0..7][col]
#pragma unroll
    for (int p = 0; p < 4; p++)
#pragma unroll
        for (int j = 0; j < 8; j++) {
            unsigned long long v = acc[p][j];
            vals[2 * p    ][j] = __uint_as_float((unsigned)(v & 0xffffffffull));
            vals[2 * p + 1][j] = __uint_as_float((unsigned)(v >> 32));
        }

    float ss[8];
#pragma unroll
    for (int i = 0; i < 8; i++) {
        float s = 0.f;
#pragma unroll
        for (int j = 0; j < 8; j++) s += vals[i][j] * vals[i][j];
        ss[i] = s;
    }
#pragma unroll
    for (int m = 1; m < 16; m <<= 1)
#pragma unroll
        for (int i = 0; i < 8; i++)
            ss[i] += __shfl_xor_sync(0xffffffffu, ss[i], m);

    float* __restrict__ dest = to_out ? dout : g_h;
#pragma unroll
    for (int i = 0; i < 8; i++) {
        int node = node0 + nl0 + i;
        if (node < N_NODES) {
            float scale = 1.f / fmaxf(sqrtf(ss[i]), 1e-12f);
            float o[8];
#pragma unroll
            for (int j = 0; j < 8; j++) {
                float v = vals[i][j] * scale;
                o[j] = relu ? fmaxf(v, 0.f) : v;
            }
            *(float4*)&dest[(size_t)node * 128 + f0] =
                make_float4(o[0], o[1], o[2], o[3]);
            *(float4*)&dest[(size_t)node * 128 + f0 + 4] =
                make_float4(o[4], o[5], o[6], o[7]);
            if (!to_out) {
                half2 hh[4];
                hh[0] = __floats2half2_rn(o[0], o[1]);
                hh[1] = __floats2half2_rn(o[2], o[3]);
                hh[2] = __floats2half2_rn(o[4], o[5]);
                hh[3] = __floats2half2_rn(o[6], o[7]);
                *(uint4*)&g_hh[(size_t)node * 128 + f0] = *(const uint4*)hh;
            }
        }
    }
}

// ---------------- launch (13 kernels, fully stateless, wide scan) ----------------
extern "C" void kernel_launch(void* const* d_in, const int* in_sizes, int n_in,
                              void* d_out, int out_size) {
    const float* x   = (const float*)d_in[0];
    const int*   ei  = (const int*)d_in[1];     // int32 (JAX x64-disabled)
    const float* Wl0 = (const float*)d_in[2];
    const float* bl0 = (const float*)d_in[3];
    const float* Wr0 = (const float*)d_in[4];
    const float* Wl1 = (const float*)d_in[5];
    const float* bl1 = (const float*)d_in[6];
    const float* Wr1 = (const float*)d_in[7];
    const float* Wl2 = (const float*)d_in[8];
    const float* bl2 = (const float*)d_in[9];
    const float* Wr2 = (const float*)d_in[10];
    float* out = (float*)d_out;

    const int NB_NODE   = (N_NODES + 255) / 256;     // 196
    const int NB_EDGE   = (N_EDGES + 255) / 256;
    const int NB_AGG128 = (N_NODES + 7) / 8;
    const int NB_AGG64  = (N_NODES / 2 + 7) / 8;
    const int NB_TRANS  = (N_NODES + 127) / 128;
    const int NB_PREP   = (X2H_ELEMS + 255) / 256;

    // prep (weights + fp16 x) — independent of CSR
    k_prep<<<NB_PREP, 256>>>(x, Wl0, Wr0, Wl1, Wr1, Wl2, Wr2);

    // CSR build (multi-block scan — the 109us single-block scan is gone)
    k_zero_cnt<<<NB_NODE, 256>>>();
    k_count<<<NB_EDGE, 256>>>(ei);
    k_scan1<<<NB_NODE, 256>>>();
    k_scan2<<<1, 256>>>(NB_NODE);
    k_scan3<<<NB_NODE, 256>>>();
    k_fill<<<NB_EDGE, 256>>>(ei);

    // layer 0: x (d=64) -> g_h/g_hh (relu)
    k_agg64h<<<NB_AGG64, 256>>>();
    k_transform<<<NB_TRANS, 256>>>(x, 0, 0, bl0, IN_CH, 1, 0, out);

    // layer 1: g_hh (d=128) -> g_h/g_hh (relu)
    k_agg128h<<<NB_AGG128, 256>>>();
    k_transform<<<NB_TRANS, 256>>>(x, 1, 1, bl1, HID, 1, 0, out);

    // layer 2: g_hh (d=128) -> out (no relu)
    k_agg128h<<<NB_AGG128, 256>>>();
    k_transform<<<NB_TRANS, 256>>>(x, 1, 2, bl2, HID, 0, 1, out);
}

// round 17
// speedup vs baseline: 1.2754x; 1.0002x over previous
#include <cuda_runtime.h>
#include <cuda_fp16.h>
#include <math.h>

#define N_NODES 50000
#define N_EDGES 800000
#define IN_CH   64
#define HID     128

// ---------------- scratch (static device globals; no allocation) ----------------
__device__ int   g_cnt[N_NODES];
__device__ int   g_deg[N_NODES];                        // node in-degree (snapshot)
__device__ int   g_off[N_NODES];
__device__ int   g_cur[N_NODES];
__device__ int   g_bsum[256];
__device__ int   g_csr[N_EDGES];                        // src node id per CSR slot (keyed by dst)
__device__ __align__(16) float  g_h[N_NODES * HID];     // hidden activations (fp32, self term)
__device__ __align__(16) __half g_hh[N_NODES * HID];    // hidden activations (fp16, gather copy)
__device__ __align__(16) __half g_xh[N_NODES * IN_CH];  // x in fp16 (gather copy)
__device__ __align__(16) float  g_mean[N_NODES * HID];  // mean-aggregated neighbor features
__device__ __align__(16) float  g_W0[(2 * IN_CH) * HID];// [K][128] k-major: Wl^T rows then Wr^T rows
__device__ __align__(16) float  g_W1[(2 * HID) * HID];
__device__ __align__(16) float  g_W2[(2 * HID) * HID];

// ---------------- packed f32x2 helpers ----------------
__device__ __forceinline__ unsigned long long pack2(float w) {
    unsigned long long r;
    unsigned u = __float_as_uint(w);
    asm("mov.b64 %0, {%1, %1};" : "=l"(r) : "r"(u));
    return r;
}
__device__ __forceinline__ void ffma2(unsigned long long& acc,
                                      unsigned long long a, unsigned long long b) {
    asm("fma.rn.f32x2 %0, %1, %2, %0;" : "+l"(acc) : "l"(a), "l"(b));
}

// ---------------- CSR build (multi-block scan, R4-proven shape) ----------------
__global__ void k_zero_cnt() {
    int i = blockIdx.x * blockDim.x + threadIdx.x;
    if (i < N_NODES) g_cnt[i] = 0;
}

// edge_index is int32 on the wire (JAX x64 disabled downgrades int64 -> int32).
__global__ void k_count(const int* __restrict__ ei) {
    int e = blockIdx.x * blockDim.x + threadIdx.x;
    if (e < N_EDGES) {
        int dst = ei[N_EDGES + e];
        if ((unsigned)dst < (unsigned)N_NODES)
            atomicAdd(&g_cnt[dst], 1);
    }
}

__global__ void k_scan1() {
    __shared__ int s[256];
    int i = blockIdx.x * 256 + threadIdx.x;
    int v = (i < N_NODES) ? g_cnt[i] : 0;
    s[threadIdx.x] = v;
    __syncthreads();
    for (int off = 1; off < 256; off <<= 1) {
        int t = (threadIdx.x >= off) ? s[threadIdx.x - off] : 0;
        __syncthreads();
        s[threadIdx.x] += t;
        __syncthreads();
    }
    if (i < N_NODES) g_off[i] = s[threadIdx.x] - v;   // exclusive within block
    if (threadIdx.x == 255) g_bsum[blockIdx.x] = s[255];
}

__global__ void k_scan2(int nb) {
    __shared__ int s[256];
    int v = (threadIdx.x < nb) ? g_bsum[threadIdx.x] : 0;
    s[threadIdx.x] = v;
    __syncthreads();
    for (int off = 1; off < 256; off <<= 1) {
        int t = (threadIdx.x >= off) ? s[threadIdx.x - off] : 0;
        __syncthreads();
        s[threadIdx.x] += t;
        __syncthreads();
    }
    g_bsum[threadIdx.x] = s[threadIdx.x] - v;         // exclusive block offsets
}

__global__ void k_scan3() {
    int i = blockIdx.x * blockDim.x + threadIdx.x;
    if (i < N_NODES) {
        int o = g_off[i] + g_bsum[i >> 8];
        g_off[i] = o;
        g_cur[i] = o;
        g_deg[i] = g_cnt[i];
    }
}

__global__ void k_fill(const int* __restrict__ ei) {
    int e = blockIdx.x * blockDim.x + threadIdx.x;
    if (e < N_EDGES) {
        int src = ei[e];
        int dst = ei[N_EDGES + e];
        if ((unsigned)dst < (unsigned)N_NODES && (unsigned)src < (unsigned)N_NODES) {
            int pos = atomicAdd(&g_cur[dst], 1);
            if ((unsigned)pos < (unsigned)N_EDGES) g_csr[pos] = src;
        }
    }
}

// ---------------- prep: weight transpose+concat (3 layers) + x fp16 copy ----------------
#define W0_ELEMS  (2 * IN_CH * HID)              // 16384
#define W12_ELEMS (2 * HID * HID)                // 32768
#define X2H_ELEMS (N_NODES * IN_CH / 2)          // half2 count
__global__ void k_prep(const float* __restrict__ x,
                       const float* __restrict__ Wl0, const float* __restrict__ Wr0,
                       const float* __restrict__ Wl1, const float* __restrict__ Wr1,
                       const float* __restrict__ Wl2, const float* __restrict__ Wr2) {
    int i = blockIdx.x * blockDim.x + threadIdx.x;
    if (i < X2H_ELEMS) {
        float2 v = ((const float2*)x)[i];
        ((half2*)g_xh)[i] = __floats2half2_rn(v.x, v.y);
    }
    if (i < W0_ELEMS) {
        int k = i >> 7, f = i & 127;
        g_W0[i] = (k < IN_CH) ? Wl0[f * IN_CH + k] : Wr0[f * IN_CH + (k - IN_CH)];
    }
    if (i < 2 * W12_ELEMS) {
        if (i < W12_ELEMS) {
            int k = i >> 7, f = i & 127;
            g_W1[i] = (k < HID) ? Wl1[f * HID + k] : Wr1[f * HID + (k - HID)];
        } else {
            int j = i - W12_ELEMS;
            int k2 = j >> 7, f2 = j & 127;
            g_W2[j] = (k2 < HID) ? Wl2[f2 * HID + k2] : Wr2[f2 * HID + (k2 - HID)];
        }
    }
}

// ---------------- aggregation d=64 (fp16 src): two nodes per warp ----------------
__global__ void k_agg64h() {
    int w    = (blockIdx.x * blockDim.x + threadIdx.x) >> 5;
    int lane = threadIdx.x & 31;
    int node = w * 2 + (lane >> 4);
    int il   = lane & 15;
    if (node >= N_NODES) return;
    int start = g_off[node];
    int cnt   = g_deg[node];
    const uint2* __restrict__ x2 = (const uint2*)g_xh;   // 16 uint2 per row
    float ax = 0.f, ay = 0.f, az = 0.f, aw = 0.f;
    for (int e = 0; e < cnt; e++) {
        int s = g_csr[start + e];
        uint2 v = x2[(size_t)s * 16 + il];
        float2 lo = __half22float2(*(const half2*)&v.x);
        float2 hi = __half22float2(*(const half2*)&v.y);
        ax += lo.x; ay += lo.y; az += hi.x; aw += hi.y;
    }
    float inv = 1.f / fmaxf((float)cnt, 1.f);
    ((float4*)g_mean)[(size_t)node * 16 + il] =
        make_float4(ax * inv, ay * inv, az * inv, aw * inv);
}

// ---------------- aggregation d=128 (fp16 src): warp per node ----------------
__global__ void k_agg128h() {
    int gw   = (blockIdx.x * blockDim.x + threadIdx.x) >> 5;
    int lane = threadIdx.x & 31;
    if (gw >= N_NODES) return;
    int start = g_off[gw];
    int cnt   = g_deg[gw];
    const uint2* __restrict__ h2 = (const uint2*)g_hh;   // 32 uint2 per row
    float ax = 0.f, ay = 0.f, az = 0.f, aw = 0.f;
    for (int e = 0; e < cnt; e++) {
        int s = g_csr[start + e];
        uint2 v = h2[(size_t)s * 32 + lane];
        float2 lo = __half22float2(*(const half2*)&v.x);
        float2 hi = __half22float2(*(const half2*)&v.y);
        ax += lo.x; ay += lo.y; az += hi.x; aw += hi.y;
    }
    float inv = 1.f / fmaxf((float)cnt, 1.f);
    ((float4*)g_mean)[(size_t)gw * 32 + lane] =
        make_float4(ax * inv, ay * inv, az * inv, aw * inv);
}

// ---------------- fused transform + L2-normalize (+relu) — R8-proven body ----------------
// out = normalize(mean@Wl^T + bias + x@Wr^T), K = 2*DIN virtual reduction.
// Block: 256 threads, tile 128 nodes x 128 f. Thread: 8 nodes x 8 cols,
// node-pair-packed f32x2 accumulators (bias folded into init).
// When writing g_h, also writes fp16 copy g_hh for the next gather.
#define AS_STRIDE 130
__global__ __launch_bounds__(256) void k_transform(
    const float* __restrict__ xin, int use_h, int layer,
    const float* __restrict__ bias, int DIN, int relu, int to_out,
    float* __restrict__ dout)
{
    const float* __restrict__ A1 = g_mean;
    const float* __restrict__ A2 = use_h ? g_h : xin;
    const float* __restrict__ W  = (layer == 0) ? g_W0 : (layer == 1) ? g_W1 : g_W2;

    __shared__ __align__(16) float As[32 * AS_STRIDE];  // [kk][node]
    __shared__ __align__(16) float Ws[32 * 128];        // [kk][f]

    const int tid   = threadIdx.x;
    const int tx    = tid & 15;          // f group
    const int ty    = tid >> 4;          // node group
    const int f0    = tx * 8;
    const int nl0   = ty * 8;
    const int node0 = blockIdx.x * 128;

    float bs[8];
#pragma unroll
    for (int j = 0; j < 8; j++) bs[j] = bias[f0 + j];

    unsigned long long acc[4][8];        // [node pair][col], bias preloaded
#pragma unroll
    for (int p = 0; p < 4; p++)
#pragma unroll
        for (int j = 0; j < 8; j++) acc[p][j] = pack2(bs[j]);

    const int K   = 2 * DIN;
    const int lkk = tid & 31;            // A loader: k within chunk
    const int lng = tid >> 5;            // A loader: node group (16 nodes)
    const int lf  = tid & 127;           // W loader: f
    const int lkg = tid >> 7;            // W loader: k group (16 kk)

    for (int c0 = 0; c0 < K; c0 += 32) {
        const float* Asrc = (c0 < DIN) ? A1 : A2;
        const int cb = (c0 < DIN) ? c0 : (c0 - DIN);
#pragma unroll
        for (int r = 0; r < 16; r++) {
            int n = lng * 16 + r;
            int node = node0 + n;
            float v = (node < N_NODES) ? Asrc[(size_t)node * DIN + cb + lkk] : 0.f;
            As[lkk * AS_STRIDE + n] = v;
        }
#pragma unroll
        for (int r = 0; r < 16; r++) {
            int kk = lkg * 16 + r;
            Ws[kk * 128 + lf] = W[(size_t)(c0 + kk) * 128 + lf];
        }
        __syncthreads();

#pragma unroll
        for (int kk = 0; kk < 32; kk++) {
            const unsigned long long* ap =
                (const unsigned long long*)&As[kk * AS_STRIDE + nl0];
            unsigned long long a0 = ap[0], a1 = ap[1], a2 = ap[2], a3 = ap[3];
            float4 w0 = *(const float4*)&Ws[kk * 128 + f0];
            float4 w1 = *(const float4*)&Ws[kk * 128 + f0 + 4];
            unsigned long long wd[8] = {
                pack2(w0.x), pack2(w0.y), pack2(w0.z), pack2(w0.w),
                pack2(w1.x), pack2(w1.y), pack2(w1.z), pack2(w1.w)};
#pragma unroll
            for (int j = 0; j < 8; j++) {
                ffma2(acc[0][j], a0, wd[j]);
                ffma2(acc[1][j], a1, wd[j]);
                ffma2(acc[2][j], a2, wd[j]);
                ffma2(acc[3][j], a3, wd[j]);
            }
        }
        __syncthreads();
    }

    // ---- epilogue: L2 norm over 16 tx lanes, relu, store (fp32 + fp16 copy) ----
    float vals[8][8];                    // [node 0..7][col]
#pragma unroll
    for (int p = 0; p < 4; p++)
#pragma unroll
        for (int j = 0; j < 8; j++) {
            unsigned long long v = acc[p][j];
            vals[2 * p    ][j] = __uint_as_float((unsigned)(v & 0xffffffffull));
            vals[2 * p + 1][j] = __uint_as_float((unsigned)(v >> 32));
        }

    float ss[8];
#pragma unroll
    for (int i = 0; i < 8; i++) {
        float s = 0.f;
#pragma unroll
        for (int j = 0; j < 8; j++) s += vals[i][j] * vals[i][j];
        ss[i] = s;
    }
#pragma unroll
    for (int m = 1; m < 16; m <<= 1)
#pragma unroll
        for (int i = 0; i < 8; i++)
            ss[i] += __shfl_xor_sync(0xffffffffu, ss[i], m);

    float* __restrict__ dest = to_out ? dout : g_h;
#pragma unroll
    for (int i = 0; i < 8; i++) {
        int node = node0 + nl0 + i;
        if (node < N_NODES) {
            float scale = 1.f / fmaxf(sqrtf(ss[i]), 1e-12f);
            float o[8];
#pragma unroll
            for (int j = 0; j < 8; j++) {
                float v = vals[i][j] * scale;
                o[j] = relu ? fmaxf(v, 0.f) : v;
            }
            *(float4*)&dest[(size_t)node * 128 + f0] =
                make_float4(o[0], o[1], o[2], o[3]);
            *(float4*)&dest[(size_t)node * 128 + f0 + 4] =
                make_float4(o[4], o[5], o[6], o[7]);
            if (!to_out) {
                half2 hh[4];
                hh[0] = __floats2half2_rn(o[0], o[1]);
                hh[1] = __floats2half2_rn(o[2], o[3]);
                hh[2] = __floats2half2_rn(o[4], o[5]);
                hh[3] = __floats2half2_rn(o[6], o[7]);
                *(uint4*)&g_hh[(size_t)node * 128 + f0] = *(const uint4*)hh;
            }
        }
    }
}

// ---------------- launch (13 kernels, fully stateless, wide scan) ----------------
extern "C" void kernel_launch(void* const* d_in, const int* in_sizes, int n_in,
                              void* d_out, int out_size) {
    const float* x   = (const float*)d_in[0];
    const int*   ei  = (const int*)d_in[1];     // int32 (JAX x64-disabled)
    const float* Wl0 = (const float*)d_in[2];
    const float* bl0 = (const float*)d_in[3];
    const float* Wr0 = (const float*)d_in[4];
    const float* Wl1 = (const float*)d_in[5];
    const float* bl1 = (const float*)d_in[6];
    const float* Wr1 = (const float*)d_in[7];
    const float* Wl2 = (const float*)d_in[8];
    const float* bl2 = (const float*)d_in[9];
    const float* Wr2 = (const float*)d_in[10];
    float* out = (float*)d_out;

    const int NB_NODE   = (N_NODES + 255) / 256;     // 196
    const int NB_EDGE   = (N_EDGES + 255) / 256;
    const int NB_AGG128 = (N_NODES + 7) / 8;
    const int NB_AGG64  = (N_NODES / 2 + 7) / 8;
    const int NB_TRANS  = (N_NODES + 127) / 128;
    const int NB_PREP   = (X2H_ELEMS + 255) / 256;

    // prep (weights + fp16 x) — independent of CSR
    k_prep<<<NB_PREP, 256>>>(x, Wl0, Wr0, Wl1, Wr1, Wl2, Wr2);

    // CSR build (multi-block scan — the 109us single-block scan is gone)
    k_zero_cnt<<<NB_NODE, 256>>>();
    k_count<<<NB_EDGE, 256>>>(ei);
    k_scan1<<<NB_NODE, 256>>>();
    k_scan2<<<1, 256>>>(NB_NODE);
    k_scan3<<<NB_NODE, 256>>>();
    k_fill<<<NB_EDGE, 256>>>(ei);

    // layer 0: x (d=64) -> g_h/g_hh (relu)
    k_agg64h<<<NB_AGG64, 256>>>();
    k_transform<<<NB_TRANS, 256>>>(x, 0, 0, bl0, IN_CH, 1, 0, out);

    // layer 1: g_hh (d=128) -> g_h/g_hh (relu)
    k_agg128h<<<NB_AGG128, 256>>>();
    k_transform<<<NB_TRANS, 256>>>(x, 1, 1, bl1, HID, 1, 0, out);

    // layer 2: g_hh (d=128) -> out (no relu)
    k_agg128h<<<NB_AGG128, 256>>>();
    k_transform<<<NB_TRANS, 256>>>(x, 1, 2, bl2, HID, 0, 1, out);
}